// round 12
// baseline (speedup 1.0000x reference)
#include <cuda_runtime.h>

// LieTransport, single-launch fused producer/consumer:
//  - Blocks 0..127 first compute 512 bilinear records each (per-(b,y,x):
//    packed float4 = {base corner offset, packed dx|dy<<16, wx, wy}),
//    publish via st.release flag (one flag per producer block).
//  - Every block then runs the proven consumer (1 float4/thread, 16 lanes/pixel,
//    4 gathers + 12-FMA blend), after acquiring ONLY its own producer's flag.
//  - Record reads use COHERENT ld.global.v4 (NOT __ldg/nc): nc may return stale
//    data for lines written by another SM within the same kernel (R11 bug).
//  - Producers are block ids 0..127 -> wave-1 resident -> no deadlock.
//  - Last finishing block resets flags + counter so graph replays are identical.

#define B 4
#define C 16
#define H 128
#define W 128
#define R 64
#define R4 (R / 4)              // 16 float4 per pixel
#define HW (H * W)
#define NPIX (B * HW)           // 65536 records
#define NPROD 128               // producer blocks
#define RECS_PER_PROD (NPIX / NPROD)     // 512
#define NBLOCKS (B * C * HW * R4 / 256)  // 65536

__device__ float4   g_rec[NPIX];
__device__ unsigned g_ready[NPROD];   // zero-initialized; reset at end of each run
__device__ unsigned g_done;

__device__ __forceinline__ void st_release(unsigned* p, unsigned v) {
    asm volatile("st.release.gpu.global.u32 [%0], %1;" :: "l"(p), "r"(v) : "memory");
}
__device__ __forceinline__ unsigned ld_acquire(const unsigned* p) {
    unsigned v;
    asm volatile("ld.acquire.gpu.global.u32 %0, [%1];" : "=r"(v) : "l"(p) : "memory");
    return v;
}
__device__ __forceinline__ float4 ld_coherent_f4(const float4* p) {
    float4 v;
    asm volatile("ld.global.v4.f32 {%0,%1,%2,%3}, [%4];"
                 : "=f"(v.x), "=f"(v.y), "=f"(v.z), "=f"(v.w) : "l"(p) : "memory");
    return v;
}

__device__ __forceinline__ float4 f4_lerp(float4 a, float4 b, float t) {
    float4 r;
    r.x = fmaf(t, b.x - a.x, a.x);
    r.y = fmaf(t, b.y - a.y, a.y);
    r.z = fmaf(t, b.z - a.z, a.z);
    r.w = fmaf(t, b.w - a.w, a.w);
    return r;
}

__global__ void __launch_bounds__(256)
lie_transport_kernel(const float4* __restrict__ h4,
                     const float* __restrict__ flow,
                     const float* __restrict__ dt,
                     float4* __restrict__ out4)
{
    int bid = blockIdx.x;
    int tid = threadIdx.x;

    // ---------- producer phase (blocks 0..127) ----------
    if (bid < NPROD) {
#pragma unroll
        for (int i = 0; i < RECS_PER_PROD / 256; ++i) {
            int t = bid * RECS_PER_PROD + i * 256 + tid;
            int x = t & (W - 1);
            int y = (t >> 7) & (H - 1);
            int b = t >> 14;

            float d   = __ldg(&dt[b]);
            float fdx = __ldg(&flow[((b * 2 + 0) * H + y) * W + x]);
            float fdy = __ldg(&flow[((b * 2 + 1) * H + y) * W + x]);

            float gx = fmaf((float)x, 2.0f / (W - 1), -1.0f) - fdx * d;
            float gy = fmaf((float)y, 2.0f / (H - 1), -1.0f) - fdy * d;

            float xs = fminf(fmaxf(((gx + 1.0f) * (float)W - 1.0f) * 0.5f, 0.0f), (float)(W - 1));
            float ys = fminf(fmaxf(((gy + 1.0f) * (float)H - 1.0f) * 0.5f, 0.0f), (float)(H - 1));

            float x0f = floorf(xs);
            float y0f = floorf(ys);
            int x0 = (int)x0f;
            int y0 = (int)y0f;
            int dx = (x0 < W - 1) ? R4 : 0;
            int dy = (y0 < H - 1) ? (W * R4) : 0;

            float4 rec;
            rec.x = __int_as_float((y0 * W + x0) * R4);
            rec.y = __int_as_float(dx | (dy << 16));
            rec.z = xs - x0f;
            rec.w = ys - y0f;
            g_rec[t] = rec;
        }
        __threadfence();
        __syncthreads();
        if (tid == 0) st_release(&g_ready[bid], 1u);
    }

    // ---------- consumer phase (all blocks) ----------
    // idx bits (fastest -> slowest): r4 (4), x (7), y (7), c (4), b (2)
    int idx  = bid * 256 + tid;
    int p    = ((idx >> 22) << 14) | ((idx >> 4) & 0x3FFF);   // record index
    int prod = p >> 9;                                        // its producer block
    int base = (idx >> 18) * (HW * R4) + (idx & (R4 - 1));    // (b*C+c) image base + r4

    // wait for this block's producer (all 16 of this block's records share one producer)
    while (ld_acquire(&g_ready[prod]) == 0u) { __nanosleep(64); }

    float4 rec = ld_coherent_f4(&g_rec[p]);   // coherent: written this kernel
    int pk = __float_as_int(rec.y);
    int dx = pk & 0xFFFF;
    int dy = pk >> 16;

    const float4* h00 = h4 + base + __float_as_int(rec.x);

    float4 v00 = __ldg(h00);
    float4 v01 = __ldg(h00 + dx);
    float4 v10 = __ldg(h00 + dy);
    float4 v11 = __ldg(h00 + dy + dx);

    float4 top = f4_lerp(v00, v01, rec.z);
    float4 bot = f4_lerp(v10, v11, rec.z);
    out4[idx]  = f4_lerp(top, bot, rec.w);

    // ---------- replay-reset protocol ----------
    __syncthreads();
    if (tid == 0) {
        __threadfence();
        unsigned old = atomicAdd(&g_done, 1u);
        if (old == (unsigned)(NBLOCKS - 1)) {
            // last block: reset flags and counter for the next (graph-replayed) run
            for (int i = 0; i < NPROD; ++i) g_ready[i] = 0u;
            __threadfence();
            g_done = 0u;
        }
    }
}

extern "C" void kernel_launch(void* const* d_in, const int* in_sizes, int n_in,
                              void* d_out, int out_size)
{
    const float* h_prev = nullptr;
    const float* flow   = nullptr;
    const float* dt     = nullptr;
    for (int i = 0; i < n_in; ++i) {
        if (in_sizes[i] == B * C * H * W * R)      h_prev = (const float*)d_in[i];
        else if (in_sizes[i] == B * 2 * H * W)     flow   = (const float*)d_in[i];
        else if (in_sizes[i] == B)                 dt     = (const float*)d_in[i];
    }

    lie_transport_kernel<<<NBLOCKS, 256>>>(
        (const float4*)h_prev, flow, dt, (float4*)d_out);
}

// round 13
// speedup vs baseline: 1.8052x; 1.8052x over previous
#include <cuda_runtime.h>

// LieTransport: out[b,c,y,x,r] = bilinear_border_sample(h_prev[b,c,:,:,r], grid(b,y,x))
// Shapes: h_prev [4,16,128,128,64] f32, flow [4,2,128,128] f32, dt [4] f32.
// Single launch. Each thread processes TWO pixels of the same (b,c) image:
// (y,x) and (y+64,x), same r4 lane. Both chains fully independent -> 8 gathers
// in flight per thread (2x MLP vs one-pixel kernels) while every warp load still
// covers full 128B lines (16 lanes per pixel). Simplified coord math:
//   xs = clip(x*128/127 - 0.5 - 64*d*fdx),  same for y.

#define B 4
#define C 16
#define H 128
#define W 128
#define R 64
#define R4 (R / 4)            // 16 float4 per pixel
#define HW (H * W)
#define HALFROWS 64
#define HALF4 (HALFROWS * W * R4)   // float4 offset of (y+64,x) within an image

__device__ __forceinline__ float4 f4_lerp(float4 a, float4 b, float t) {
    float4 r;
    r.x = fmaf(t, b.x - a.x, a.x);
    r.y = fmaf(t, b.y - a.y, a.y);
    r.z = fmaf(t, b.z - a.z, a.z);
    r.w = fmaf(t, b.w - a.w, a.w);
    return r;
}

__global__ void __launch_bounds__(256, 5)
lie_transport_kernel(const float4* __restrict__ h4,
                     const float* __restrict__ flow,
                     const float* __restrict__ dt,
                     float4* __restrict__ out4)
{
    // idx bits (fastest -> slowest): r4 (4), x (7), y (6: 0..63), c (4), b (2)
    int idx = blockIdx.x * blockDim.x + threadIdx.x;   // 0 .. 2^23-1
    int r4 = idx & (R4 - 1);
    int x  = (idx >> 4) & (W - 1);
    int y  = (idx >> 11) & (HALFROWS - 1);
    int c  = (idx >> 17) & (C - 1);
    int b  = idx >> 21;

    // ---- coords for both pixels (independent chains) ----
    float d  = __ldg(&dt[b]);
    float md = -64.0f * d;

    const float* fb = flow + b * 2 * HW;
    float fdx0 = __ldg(fb + y * W + x);
    float fdy0 = __ldg(fb + HW + y * W + x);
    float fdx1 = __ldg(fb + (y + HALFROWS) * W + x);
    float fdy1 = __ldg(fb + HW + (y + HALFROWS) * W + x);

    const float SCL = 128.0f / 127.0f;
    float xb  = fmaf((float)x, SCL, -0.5f);
    float yb0 = fmaf((float)y, SCL, -0.5f);
    float yb1 = fmaf((float)(y + HALFROWS), SCL, -0.5f);

    float xs0 = fminf(fmaxf(fmaf(fdx0, md, xb),  0.0f), (float)(W - 1));
    float ys0 = fminf(fmaxf(fmaf(fdy0, md, yb0), 0.0f), (float)(H - 1));
    float xs1 = fminf(fmaxf(fmaf(fdx1, md, xb),  0.0f), (float)(W - 1));
    float ys1 = fminf(fmaxf(fmaf(fdy1, md, yb1), 0.0f), (float)(H - 1));

    float x0f0 = floorf(xs0), y0f0 = floorf(ys0);
    float x0f1 = floorf(xs1), y0f1 = floorf(ys1);
    float wx0 = xs0 - x0f0, wy0 = ys0 - y0f0;
    float wx1 = xs1 - x0f1, wy1 = ys1 - y0f1;

    int x00 = (int)x0f0, y00 = (int)y0f0;
    int x01 = (int)x0f1, y01 = (int)y0f1;
    int dx0 = (x00 < W - 1) ? R4 : 0;
    int dy0 = (y00 < H - 1) ? (W * R4) : 0;
    int dx1 = (x01 < W - 1) ? R4 : 0;
    int dy1 = (y01 < H - 1) ? (W * R4) : 0;

    int ibase = (b * C + c) * (HW * R4) + r4;          // image base + lane
    const float4* p0 = h4 + ibase + (y00 * W + x00) * R4;
    const float4* p1 = h4 + ibase + (y01 * W + x01) * R4;

    // ---- 8 independent gathers ----
    float4 a00 = __ldg(p0);
    float4 a01 = __ldg(p0 + dx0);
    float4 a10 = __ldg(p0 + dy0);
    float4 a11 = __ldg(p0 + dy0 + dx0);
    float4 b00 = __ldg(p1);
    float4 b01 = __ldg(p1 + dx1);
    float4 b10 = __ldg(p1 + dy1);
    float4 b11 = __ldg(p1 + dy1 + dx1);

    // ---- blends + stores ----
    int obase = ibase + (y * W + x) * R4;
    float4 t0 = f4_lerp(a00, a01, wx0);
    float4 u0 = f4_lerp(a10, a11, wx0);
    out4[obase] = f4_lerp(t0, u0, wy0);

    float4 t1 = f4_lerp(b00, b01, wx1);
    float4 u1 = f4_lerp(b10, b11, wx1);
    out4[obase + HALF4] = f4_lerp(t1, u1, wy1);
}

extern "C" void kernel_launch(void* const* d_in, const int* in_sizes, int n_in,
                              void* d_out, int out_size)
{
    const float* h_prev = nullptr;
    const float* flow   = nullptr;
    const float* dt     = nullptr;
    for (int i = 0; i < n_in; ++i) {
        if (in_sizes[i] == B * C * H * W * R)      h_prev = (const float*)d_in[i];
        else if (in_sizes[i] == B * 2 * H * W)     flow   = (const float*)d_in[i];
        else if (in_sizes[i] == B)                 dt     = (const float*)d_in[i];
    }

    int total = B * C * HW * R4 / 2;               // 8,388,608 threads
    lie_transport_kernel<<<total / 256, 256>>>(
        (const float4*)h_prev, flow, dt, (float4*)d_out);
}

// round 14
// speedup vs baseline: 1.8665x; 1.0339x over previous
#include <cuda_runtime.h>

// LieTransport, two-phase with PDL overlap (best-known structure, refined):
//  1) precompute per-(b,y,x) bilinear records (int4 corner offsets + float2 w),
//     single CTA wave: 128 blocks x 512 threads.
//  2) main gather kernel: 1 float4/thread, 16 lanes/pixel, 128-thread blocks
//     (16 blocks/SM -> finer scheduling granularity, higher achieved occupancy).

#define B 4
#define C 16
#define H 128
#define W 128
#define R 64
#define R4 (R / 4)            // 16 float4 per pixel
#define HW (H * W)
#define NPIX (B * HW)         // 65536 records

__device__ int4   g_cidx[NPIX];   // corner float4-offsets within one (b,c) image
__device__ float2 g_wxy[NPIX];    // (wx, wy)

__global__ void __launch_bounds__(512)
precompute_kernel(const float* __restrict__ flow,
                  const float* __restrict__ dt)
{
    int t = blockIdx.x * blockDim.x + threadIdx.x;   // 0 .. NPIX-1
    int x = t & (W - 1);
    int y = (t >> 7) & (H - 1);
    int b = t >> 14;

    float d   = __ldg(&dt[b]);
    float fdx = __ldg(&flow[((b * 2 + 0) * H + y) * W + x]);
    float fdy = __ldg(&flow[((b * 2 + 1) * H + y) * W + x]);

    float gx = fmaf((float)x, 2.0f / (W - 1), -1.0f) - fdx * d;
    float gy = fmaf((float)y, 2.0f / (H - 1), -1.0f) - fdy * d;

    float xs = fminf(fmaxf(((gx + 1.0f) * (float)W - 1.0f) * 0.5f, 0.0f), (float)(W - 1));
    float ys = fminf(fmaxf(((gy + 1.0f) * (float)H - 1.0f) * 0.5f, 0.0f), (float)(H - 1));

    float x0f = floorf(xs);
    float y0f = floorf(ys);

    int x0 = (int)x0f;
    int y0 = (int)y0f;
    int x1 = min(x0 + 1, W - 1);
    int y1 = min(y0 + 1, H - 1);

    int4 ci;
    ci.x = (y0 * W + x0) * R4;
    ci.y = (y0 * W + x1) * R4;
    ci.z = (y1 * W + x0) * R4;
    ci.w = (y1 * W + x1) * R4;
    g_cidx[t] = ci;
    g_wxy[t]  = make_float2(xs - x0f, ys - y0f);

#if __CUDA_ARCH__ >= 900
    cudaTriggerProgrammaticLaunchCompletion();
#endif
}

__device__ __forceinline__ float4 f4_lerp(float4 a, float4 b, float t) {
    float4 r;
    r.x = fmaf(t, b.x - a.x, a.x);
    r.y = fmaf(t, b.y - a.y, a.y);
    r.z = fmaf(t, b.z - a.z, a.z);
    r.w = fmaf(t, b.w - a.w, a.w);
    return r;
}

__global__ void __launch_bounds__(128)
lie_transport_kernel(const float4* __restrict__ h4,
                     float4* __restrict__ out4)
{
    // idx bits (fastest -> slowest): r4 (4b), x (7b), y (7b), c (4b), b (2b)
    int idx = blockIdx.x * blockDim.x + threadIdx.x;   // 0 .. 2^24-1
    int r4  = idx & (R4 - 1);

    // record index = (b<<14) | (y<<7) | x  -- independent of records
    int p    = ((idx >> 22) << 14) | ((idx >> 4) & 0x3FFF);
    int base = (idx >> 18) * (HW * R4) + r4;           // (b*C + c) image base

#if __CUDA_ARCH__ >= 900
    cudaGridDependencySynchronize();                   // wait for precompute results
#endif

    int4   ci = __ldg(&g_cidx[p]);
    float2 w  = __ldg(&g_wxy[p]);

    float4 v00 = __ldg(h4 + base + ci.x);
    float4 v01 = __ldg(h4 + base + ci.y);
    float4 v10 = __ldg(h4 + base + ci.z);
    float4 v11 = __ldg(h4 + base + ci.w);

    float4 top = f4_lerp(v00, v01, w.x);
    float4 bot = f4_lerp(v10, v11, w.x);
    out4[idx]  = f4_lerp(top, bot, w.y);
}

extern "C" void kernel_launch(void* const* d_in, const int* in_sizes, int n_in,
                              void* d_out, int out_size)
{
    const float* h_prev = nullptr;
    const float* flow   = nullptr;
    const float* dt     = nullptr;
    for (int i = 0; i < n_in; ++i) {
        if (in_sizes[i] == B * C * H * W * R)      h_prev = (const float*)d_in[i];
        else if (in_sizes[i] == B * 2 * H * W)     flow   = (const float*)d_in[i];
        else if (in_sizes[i] == B)                 dt     = (const float*)d_in[i];
    }

    // Primary: compute records in a single CTA wave (128 blocks x 512 thr)
    precompute_kernel<<<NPIX / 512, 512>>>(flow, dt);

    // Secondary: PDL launch overlapping the primary's tail; 128-thread blocks
    int total = B * C * HW * R4;                   // 16,777,216 threads
    cudaLaunchConfig_t cfg = {};
    cfg.gridDim  = dim3(total / 128);              // 131072 blocks
    cfg.blockDim = dim3(128);
    cfg.dynamicSmemBytes = 0;
    cfg.stream = 0;
    cudaLaunchAttribute attrs[1];
    attrs[0].id = cudaLaunchAttributeProgrammaticStreamSerialization;
    attrs[0].val.programmaticStreamSerializationAllowed = 1;
    cfg.attrs = attrs;
    cfg.numAttrs = 1;
    cudaLaunchKernelEx(&cfg, lie_transport_kernel,
                       (const float4*)h_prev, (float4*)d_out);
}

// round 15
// speedup vs baseline: 2.1485x; 1.1511x over previous
#include <cuda_runtime.h>

// LieTransport, two-phase with PDL overlap, EARLY trigger:
//  1) precompute per-(b,y,x) bilinear records (int4 corner offsets + float2 w).
//     cudaTriggerProgrammaticLaunchCompletion() fires at the TOP of the primary:
//     the secondary grid's launch pipeline overlaps the primary's execution.
//     Data safety comes from cudaGridDependencySynchronize in the secondary,
//     which waits for full primary completion regardless of trigger timing.
//  2) main gather kernel (proven 94.0us config): 1 float4/thread, 16 lanes/pixel,
//     256-thread blocks.

#define B 4
#define C 16
#define H 128
#define W 128
#define R 64
#define R4 (R / 4)            // 16 float4 per pixel
#define HW (H * W)
#define NPIX (B * HW)         // 65536 records

__device__ int4   g_cidx[NPIX];   // corner float4-offsets within one (b,c) image
__device__ float2 g_wxy[NPIX];    // (wx, wy)

__global__ void __launch_bounds__(256)
precompute_kernel(const float* __restrict__ flow,
                  const float* __restrict__ dt)
{
#if __CUDA_ARCH__ >= 900
    cudaTriggerProgrammaticLaunchCompletion();   // let secondary start launching NOW
#endif

    int t = blockIdx.x * blockDim.x + threadIdx.x;   // 0 .. NPIX-1
    int x = t & (W - 1);
    int y = (t >> 7) & (H - 1);
    int b = t >> 14;

    float d   = __ldg(&dt[b]);
    float fdx = __ldg(&flow[((b * 2 + 0) * H + y) * W + x]);
    float fdy = __ldg(&flow[((b * 2 + 1) * H + y) * W + x]);

    float gx = fmaf((float)x, 2.0f / (W - 1), -1.0f) - fdx * d;
    float gy = fmaf((float)y, 2.0f / (H - 1), -1.0f) - fdy * d;

    float xs = fminf(fmaxf(((gx + 1.0f) * (float)W - 1.0f) * 0.5f, 0.0f), (float)(W - 1));
    float ys = fminf(fmaxf(((gy + 1.0f) * (float)H - 1.0f) * 0.5f, 0.0f), (float)(H - 1));

    float x0f = floorf(xs);
    float y0f = floorf(ys);

    int x0 = (int)x0f;
    int y0 = (int)y0f;
    int x1 = min(x0 + 1, W - 1);
    int y1 = min(y0 + 1, H - 1);

    int4 ci;
    ci.x = (y0 * W + x0) * R4;
    ci.y = (y0 * W + x1) * R4;
    ci.z = (y1 * W + x0) * R4;
    ci.w = (y1 * W + x1) * R4;
    g_cidx[t] = ci;
    g_wxy[t]  = make_float2(xs - x0f, ys - y0f);
}

__device__ __forceinline__ float4 f4_lerp(float4 a, float4 b, float t) {
    float4 r;
    r.x = fmaf(t, b.x - a.x, a.x);
    r.y = fmaf(t, b.y - a.y, a.y);
    r.z = fmaf(t, b.z - a.z, a.z);
    r.w = fmaf(t, b.w - a.w, a.w);
    return r;
}

__global__ void __launch_bounds__(256)
lie_transport_kernel(const float4* __restrict__ h4,
                     float4* __restrict__ out4)
{
    // idx bits (fastest -> slowest): r4 (4b), x (7b), y (7b), c (4b), b (2b)
    int idx = blockIdx.x * blockDim.x + threadIdx.x;   // 0 .. 2^24-1
    int r4  = idx & (R4 - 1);

    // record index = (b<<14) | (y<<7) | x  -- independent of records
    int p    = ((idx >> 22) << 14) | ((idx >> 4) & 0x3FFF);
    int base = (idx >> 18) * (HW * R4) + r4;           // (b*C + c) image base

#if __CUDA_ARCH__ >= 900
    cudaGridDependencySynchronize();                   // wait for primary completion
#endif

    int4   ci = __ldg(&g_cidx[p]);
    float2 w  = __ldg(&g_wxy[p]);

    float4 v00 = __ldg(h4 + base + ci.x);
    float4 v01 = __ldg(h4 + base + ci.y);
    float4 v10 = __ldg(h4 + base + ci.z);
    float4 v11 = __ldg(h4 + base + ci.w);

    float4 top = f4_lerp(v00, v01, w.x);
    float4 bot = f4_lerp(v10, v11, w.x);
    out4[idx]  = f4_lerp(top, bot, w.y);
}

extern "C" void kernel_launch(void* const* d_in, const int* in_sizes, int n_in,
                              void* d_out, int out_size)
{
    const float* h_prev = nullptr;
    const float* flow   = nullptr;
    const float* dt     = nullptr;
    for (int i = 0; i < n_in; ++i) {
        if (in_sizes[i] == B * C * H * W * R)      h_prev = (const float*)d_in[i];
        else if (in_sizes[i] == B * 2 * H * W)     flow   = (const float*)d_in[i];
        else if (in_sizes[i] == B)                 dt     = (const float*)d_in[i];
    }

    // Primary: compute records (256 blocks x 256 threads)
    precompute_kernel<<<NPIX / 256, 256>>>(flow, dt);

    // Secondary: PDL launch; its launch pipeline overlaps the primary
    int total = B * C * HW * R4;                   // 16,777,216 threads
    cudaLaunchConfig_t cfg = {};
    cfg.gridDim  = dim3(total / 256);              // 65536 blocks
    cfg.blockDim = dim3(256);
    cfg.dynamicSmemBytes = 0;
    cfg.stream = 0;
    cudaLaunchAttribute attrs[1];
    attrs[0].id = cudaLaunchAttributeProgrammaticStreamSerialization;
    attrs[0].val.programmaticStreamSerializationAllowed = 1;
    cfg.attrs = attrs;
    cfg.numAttrs = 1;
    cudaLaunchKernelEx(&cfg, lie_transport_kernel,
                       (const float4*)h_prev, (float4*)d_out);
}